// round 1
// baseline (speedup 1.0000x reference)
#include <cuda_runtime.h>
#include <cuda_bf16.h>
#include <math.h>

// ============================================================================
// SphericalHarmonicsShellsConv — GB300 (sm_103a)
//
// Shapes (fixed by the problem):
//   B=4, N=4096, V=2048, P=32, C=16
//   x0:(B,N,1,16) x1:(B,N,3,16) x2:(B,N,5,16) x3:(B,N,7,16)
//   patches_idx:(B,V,P,2) int32, kernels:(B,V,P,30) f32
// Signal channel layout (concat): c in [0,256):
//   l=0: [0,16)   rowlen 16   (x0)
//   l=1: [16,64)  rowlen 48   (x1)   c = 16 + m*16+ch
//   l=2: [64,144) rowlen 80   (x2)
//   l=3: [144,256) rowlen 112 (x3)
// y rows (30): j=0:[0,4) j=1:[4,13) j=2:[13,23) j=3:[23,30); within block j:
//   row = y_off[j] + n*(4-j) + i,  n in [0,2j+1), i in [0,4-j)
// Outputs (flattened tuple, concatenated):
//   out[J] shape (B,V,2J+1,chJ), chJ = {160,336,384,320}
// ============================================================================

#define B_ 4
#define N_ 4096
#define V_ 2048
#define P_ 32
#define BV_ (B_*V_)

#define NGROUPS 333          // 5328 output elements / 16 channels
#define MAXNNZ 64            // max CG pairs per group (<=49 actual)

// pair: {coef, ybase} packed as float2 (y = bitcast int ybase)
__device__ float2 g_pairs[NGROUPS * MAXNNZ];
__device__ int2   g_meta[NGROUPS];     // x = (J<<16)|local_base, y = nnz
__device__ float  d_cg[27 * 343];      // dense real CG tables, stride 343/combo

// ---------------------------------------------------------------------------
// Init 1: real-basis Clebsch-Gordan coefficients (mirrors reference exactly)
// ---------------------------------------------------------------------------
__device__ __forceinline__ double dfact(int n) {
    const double f[16] = {1.,1.,2.,6.,24.,120.,720.,5040.,40320.,362880.,
                          3628800.,39916800.,479001600.,6227020800.,
                          87178291200.,1307674368000.};
    return f[n];
}

__device__ double su2_cg(int j1,int m1,int j2,int m2,int j3,int m3) {
    if (m3 != m1 + m2) return 0.0;
    int vmin = max(max(-j1 + j2 + m3, -j1 + m1), 0);
    int vmax = min(min(j2 + j3 + m1, j3 - j1 + j2), j3 + m3);
    double C = sqrt((2.0*j3 + 1.0) * dfact(j3+j1-j2) * dfact(j3-j1+j2) * dfact(j1+j2-j3)
                    * dfact(j3+m3) * dfact(j3-m3)
                    / (dfact(j1+j2+j3+1) * dfact(j1-m1) * dfact(j1+m1)
                       * dfact(j2-m2) * dfact(j2+m2)));
    double S = 0.0;
    for (int v = vmin; v <= vmax; v++) {
        double sgn = ((v + j2 + m2) & 1) ? -1.0 : 1.0;
        S += sgn * dfact(j2+j3+m1-v) * dfact(j1-m1+v)
             / (dfact(v) * dfact(j3-j1+j2-v) * dfact(j3+m3-v) * dfact(v+j1-j2-m3));
    }
    return C * S;
}

// Q = (-i)^l * q_real_to_complex(l); returns entry (r, c)
__device__ void qmat(int l, int r, int c, double& re, double& im) {
    const double s2 = 0.7071067811865475244;
    int m = r - l;
    double qr = 0.0, qi = 0.0;
    if (m < 0) {
        if (c == l - m)      qr =  s2;     // col l+|m|
        else if (c == l + m) qi = -s2;     // col l-|m|
    } else if (m == 0) {
        if (c == l) qr = 1.0;
    } else {
        double sgn = (m & 1) ? -1.0 : 1.0;
        if (c == l + m)      qr = sgn * s2;
        else if (c == l - m) qi = sgn * s2;
    }
    switch (l & 3) {   // multiply by (-i)^l
        case 0: re =  qr; im =  qi; break;
        case 1: re =  qi; im = -qr; break;
        case 2: re = -qr; im = -qi; break;
        default: re = -qi; im =  qr; break;
    }
}

__device__ __forceinline__ int combo_index(int j, int l, int J) {
    int idx = 0;
    for (int jj = 1; jj <= 3; jj++)
        for (int ll = 1; ll <= 3; ll++) {
            int lo = abs(jj - ll), hi = min(jj + ll, 3);
            for (int JJ = lo; JJ <= hi; JJ++) {
                if (jj == j && ll == l && JJ == J) return idx;
                idx++;
            }
        }
    return -1;
}

__global__ void init_cg_kernel() {
    int combo = blockIdx.x;
    // decode combo -> (j,l,J)
    int j = -1, l = -1, J = -1;
    {
        int idx = 0;
        for (int jj = 1; jj <= 3 && j < 0; jj++)
            for (int ll = 1; ll <= 3 && j < 0; ll++) {
                int lo = abs(jj - ll), hi = min(jj + ll, 3);
                for (int JJ = lo; JJ <= hi; JJ++) {
                    if (idx == combo) { j = jj; l = ll; J = JJ; break; }
                    idx++;
                }
            }
    }
    if (j < 0) return;
    int dl = 2*l + 1, dJ = 2*J + 1, dj = 2*j + 1;
    int tot = dj * dl * dJ;
    for (int e = threadIdx.x; e < tot; e += blockDim.x) {
        int pp  = e % dJ;
        int rem = e / dJ;
        int b   = rem % dl;
        int a   = rem / dl;
        double accR = 0.0;
        for (int i = 0; i < dj; i++) {
            double q1r, q1i; qmat(j, i, a, q1r, q1i);
            if (q1r == 0.0 && q1i == 0.0) continue;
            int m1 = i - j;
            for (int k = 0; k < dl; k++) {
                int m2 = k - l, m3 = m1 + m2;
                if (m3 < -J || m3 > J) continue;
                double q2r, q2i; qmat(l, k, b, q2r, q2i);
                if (q2r == 0.0 && q2i == 0.0) continue;
                double s = su2_cg(j, m1, l, m2, J, m3);
                if (s == 0.0) continue;
                double q3r, q3i; qmat(J, J + m3, pp, q3r, q3i);
                q3i = -q3i;   // conj
                double tr = q1r*q2r - q1i*q2i, ti = q1r*q2i + q1i*q2r;
                double ur = tr*q3r - ti*q3i;
                accR += ur * s;
            }
        }
        d_cg[combo * 343 + e] = (float)accR;
    }
}

// ---------------------------------------------------------------------------
// Init 2: build the 333-group sparse program
// ---------------------------------------------------------------------------
struct Seg { signed char type, j, l; short cstart; };   // type: 0=D0(l=0), 1=D1(j=0), 2=CG, -1=end

__global__ void init_prog_kernel() {
    int g = blockIdx.x * blockDim.x + threadIdx.x;
    if (g >= NGROUPS) return;

    const int gcum[5]    = {0, 10, 73, 193, 333};
    const int gperrow[4] = {10, 21, 24, 20};
    const int chJ[4]     = {160, 336, 384, 320};
    const int yoff[4]    = {0, 4, 13, 23};
    const int coff[4]    = {0, 16, 64, 144};

    const Seg segJ0[] = {{0,0,0,0},{2,1,1,64},{2,2,2,112},{2,3,3,144},{-1,0,0,160}};
    const Seg segJ1[] = {{0,1,0,0},{1,0,1,48},{2,1,1,112},{2,2,1,160},{2,1,2,192},
                         {2,2,2,240},{2,3,2,272},{2,2,3,288},{2,3,3,320},{-1,0,0,336}};
    const Seg segJ2[] = {{0,2,0,0},{1,0,2,32},{2,1,1,96},{2,2,1,144},{2,3,1,176},
                         {2,1,2,192},{2,2,2,240},{2,3,2,272},{2,1,3,288},{2,2,3,336},
                         {2,3,3,368},{-1,0,0,384}};
    const Seg segJ3[] = {{0,3,0,0},{1,0,3,16},{2,2,1,80},{2,3,1,112},{2,1,2,128},
                         {2,2,2,176},{2,3,2,208},{2,1,3,224},{2,2,3,272},{2,3,3,304},
                         {-1,0,0,320}};
    const Seg* segs[4] = {segJ0, segJ1, segJ2, segJ3};

    int J  = (g < 10) ? 0 : (g < 73) ? 1 : (g < 193) ? 2 : 3;
    int rl = g - gcum[J];
    int p  = rl / gperrow[J];
    int c  = (rl % gperrow[J]) * 16;

    // find segment containing c
    const Seg* st = segs[J];
    int si = 0;
    while (st[si + 1].type != -1 && st[si + 1].cstart <= c) si++;
    Seg sg = st[si];
    int cl = c - sg.cstart;
    int i  = cl >> 4;

    float2* out = &g_pairs[g * MAXNNZ];
    int n = 0;
    if (sg.type == 0) {              // l=0 direct, j=J: y[yoff[J]+p*(4-J)+i, ch]
        out[n].x = 1.0f;
        out[n].y = __int_as_float((yoff[J] + p * (4 - J) + i) * 256);
        n++;
    } else if (sg.type == 1) {       // j=0 direct, l=J: y[i, coff[J]+p*16+ch]
        out[n].x = 1.0f;
        out[n].y = __int_as_float(i * 256 + coff[J] + p * 16);
        n++;
    } else {                         // CG contraction
        int j = sg.j, l = sg.l;
        int cb = combo_index(j, l, J) * 343;
        int dl = 2*l + 1, dJ = 2*J + 1;
        for (int nn = 0; nn < 2*j + 1; nn++)
            for (int m = 0; m < dl; m++) {
                float coef = d_cg[cb + (nn * dl + m) * dJ + p];
                if (fabsf(coef) > 1e-10f) {
                    out[n].x = coef;
                    out[n].y = __int_as_float((yoff[j] + nn * (4 - j) + i) * 256
                                              + coff[l] + m * 16);
                    n++;
                }
            }
    }
    g_meta[g] = make_int2((J << 16) | (p * chJ[J] + c), n);
}

// ---------------------------------------------------------------------------
// Main kernel: one CTA per (b,v)
// ---------------------------------------------------------------------------
__global__ __launch_bounds__(256)
void conv_kernel(const float* __restrict__ x0, const float* __restrict__ x1,
                 const float* __restrict__ x2, const float* __restrict__ x3,
                 const int*   __restrict__ patches,
                 const float* __restrict__ kernels,
                 float* __restrict__ out)
{
    __shared__ float Ksm[32][32];            // K[p][y], padded to 32
    __shared__ int   rowIdx[32];
    __shared__ __align__(16) float ysm[30 * 256];

    const int bv  = blockIdx.x;
    const int tid = threadIdx.x;

    // stage K (32x30) and patch row indices
    const float* kp = kernels + (size_t)bv * (P_ * 30);
    for (int t = tid; t < P_ * 30; t += 256) {
        int pr = t / 30;
        Ksm[pr][t - pr * 30] = kp[t];
    }
    if (tid < P_) {
        int2 pi = ((const int2*)patches)[(size_t)bv * P_ + tid];
        rowIdx[tid] = pi.x * N_ + pi.y;
    }

    // column -> source decode
    const float* xb; int rowlen, cloc;
    if (tid < 16)       { xb = x0; rowlen = 16;  cloc = tid;       }
    else if (tid < 64)  { xb = x1; rowlen = 48;  cloc = tid - 16;  }
    else if (tid < 144) { xb = x2; rowlen = 80;  cloc = tid - 64;  }
    else                { xb = x3; rowlen = 112; cloc = tid - 144; }

    __syncthreads();

    // y[yrow, c=tid] = sum_p K[p,yrow] * g[p,c]
    float acc[30];
    #pragma unroll
    for (int y = 0; y < 30; y++) acc[y] = 0.0f;

    #pragma unroll 4
    for (int p = 0; p < P_; p++) {
        float gv = __ldg(xb + (long)rowIdx[p] * rowlen + cloc);
        #pragma unroll
        for (int y = 0; y < 30; y++)
            acc[y] = fmaf(Ksm[p][y], gv, acc[y]);
    }

    #pragma unroll
    for (int y = 0; y < 30; y++) ysm[y * 256 + tid] = acc[y];
    __syncthreads();

    // epilogue: 333 groups x 4 quarters, float4 per item
    const size_t outBase[4] = {0, 1310720, 9568256, 25296896};
    const int    slab[4]    = {160, 1008, 1920, 2240};

    for (int item = tid; item < NGROUPS * 4; item += 256) {
        int g = item >> 2, q = item & 3;
        int2 gm = g_meta[g];
        int nnz = gm.y;
        const float2* pr = &g_pairs[g * MAXNNZ];
        float4 a = make_float4(0.f, 0.f, 0.f, 0.f);
        for (int k = 0; k < nnz; k++) {
            float2 rec = pr[k];
            int ybase = __float_as_int(rec.y);
            const float4 yv = *(const float4*)&ysm[ybase + q * 4];
            a.x = fmaf(rec.x, yv.x, a.x);
            a.y = fmaf(rec.x, yv.y, a.y);
            a.z = fmaf(rec.x, yv.z, a.z);
            a.w = fmaf(rec.x, yv.w, a.w);
        }
        int J = gm.x >> 16;
        int local = gm.x & 0xffff;
        size_t off = outBase[J] + (size_t)bv * slab[J] + local + q * 4;
        *(float4*)&out[off] = a;
    }
}

// ---------------------------------------------------------------------------
extern "C" void kernel_launch(void* const* d_in, const int* in_sizes, int n_in,
                              void* d_out, int out_size) {
    const float* x0      = (const float*)d_in[0];
    const float* x1      = (const float*)d_in[1];
    const float* x2      = (const float*)d_in[2];
    const float* x3      = (const float*)d_in[3];
    const int*   patches = (const int*)d_in[4];
    const float* kernels = (const float*)d_in[5];
    float*       out     = (float*)d_out;

    init_cg_kernel<<<27, 128>>>();
    init_prog_kernel<<<2, 256>>>();
    conv_kernel<<<BV_, 256>>>(x0, x1, x2, x3, patches, kernels, out);
}

// round 5
// speedup vs baseline: 1.3655x; 1.3655x over previous
#include <cuda_runtime.h>
#include <cuda_bf16.h>
#include <math.h>

// ============================================================================
// SphericalHarmonicsShellsConv — GB300 (sm_103a)   Round 4
//   (R1-proven conv structure + fp32 init + float4 epilogue; NO inline PTX)
//   B=4, N=4096, V=2048, P=32, C=16
// Signal channel layout (concat, 256 cols):
//   l=0: [0,16) rowlen16 | l=1: [16,64) rowlen48 | l=2: [64,144) rowlen80
//   l=3: [144,256) rowlen112
// y rows (30): yoff={0,4,13,23}; row = yoff[j] + n*(4-j) + i
// Outputs: out[J] shape (B,V,2J+1,chJ), chJ={160,336,384,320}
// ============================================================================

#define B_ 4
#define N_ 4096
#define V_ 2048
#define P_ 32
#define BV_ (B_*V_)

#define NGROUPS 333          // 5328 output elements / 16 channels
#define MAXNNZ 64            // max CG pairs per group (<=50 incl. pad)

// pair: {coef, ybase} packed as float2 (y = bitcast int ybase)
__device__ float2 g_pairs[NGROUPS * MAXNNZ];
__device__ int2   g_meta[NGROUPS];     // x = (J<<16)|local_base, y = nnz (even)
__device__ float  d_cg[27 * 343];      // dense real CG tables, stride 343/combo

// ---------------------------------------------------------------------------
// Init 1: real-basis Clebsch-Gordan coefficients — fp32, one thread per entry
// (all factorials used are <= 10! < 2^24, exact in fp32)
// ---------------------------------------------------------------------------
__device__ __forceinline__ float ffact(int n) {
    const float f[11] = {1.f,1.f,2.f,6.f,24.f,120.f,720.f,5040.f,40320.f,
                         362880.f,3628800.f};
    return f[n];
}

__device__ float su2_cg_f(int j1,int m1,int j2,int m2,int j3,int m3) {
    if (m3 != m1 + m2) return 0.0f;
    int vmin = max(max(-j1 + j2 + m3, -j1 + m1), 0);
    int vmax = min(min(j2 + j3 + m1, j3 - j1 + j2), j3 + m3);
    float C = sqrtf((2.f*j3 + 1.f) * ffact(j3+j1-j2) * ffact(j3-j1+j2) * ffact(j1+j2-j3)
                    * ffact(j3+m3) * ffact(j3-m3)
                    / (ffact(j1+j2+j3+1) * ffact(j1-m1) * ffact(j1+m1)
                       * ffact(j2-m2) * ffact(j2+m2)));
    float S = 0.0f;
    for (int v = vmin; v <= vmax; v++) {
        float sgn = ((v + j2 + m2) & 1) ? -1.0f : 1.0f;
        S += sgn * ffact(j2+j3+m1-v) * ffact(j1-m1+v)
             / (ffact(v) * ffact(j3-j1+j2-v) * ffact(j3+m3-v) * ffact(v+j1-j2-m3));
    }
    return C * S;
}

// Q = (-i)^l * q_real_to_complex(l); entry (r, c)
__device__ void qmat_f(int l, int r, int c, float& re, float& im) {
    const float s2 = 0.70710678118654752f;
    int m = r - l;
    float qr = 0.0f, qi = 0.0f;
    if (m < 0) {
        if (c == l - m)      qr =  s2;
        else if (c == l + m) qi = -s2;
    } else if (m == 0) {
        if (c == l) qr = 1.0f;
    } else {
        float sgn = (m & 1) ? -1.0f : 1.0f;
        if (c == l + m)      qr = sgn * s2;
        else if (c == l - m) qi = sgn * s2;
    }
    switch (l & 3) {
        case 0: re =  qr; im =  qi; break;
        case 1: re =  qi; im = -qr; break;
        case 2: re = -qr; im = -qi; break;
        default: re = -qi; im =  qr; break;
    }
}

__device__ __forceinline__ void combo_decode(int combo, int& j, int& l, int& J) {
    j = -1;
    int idx = 0;
    for (int jj = 1; jj <= 3; jj++)
        for (int ll = 1; ll <= 3; ll++) {
            int lo = abs(jj - ll), hi = min(jj + ll, 3);
            for (int JJ = lo; JJ <= hi; JJ++) {
                if (idx == combo) { j = jj; l = ll; J = JJ; return; }
                idx++;
            }
        }
}

__device__ __forceinline__ int combo_index(int j, int l, int J) {
    int idx = 0;
    for (int jj = 1; jj <= 3; jj++)
        for (int ll = 1; ll <= 3; ll++) {
            int lo = abs(jj - ll), hi = min(jj + ll, 3);
            for (int JJ = lo; JJ <= hi; JJ++) {
                if (jj == j && ll == l && JJ == J) return idx;
                idx++;
            }
        }
    return -1;
}

__global__ void init_cg_kernel() {
    int gid = blockIdx.x * blockDim.x + threadIdx.x;
    if (gid >= 27 * 343) return;
    int combo = gid / 343;
    int e     = gid - combo * 343;

    int j, l, J;
    combo_decode(combo, j, l, J);
    int dl = 2*l + 1, dJ = 2*J + 1, dj = 2*j + 1;
    int tot = dj * dl * dJ;
    if (e >= tot) { d_cg[gid] = 0.0f; return; }

    int pp  = e % dJ;
    int rem = e / dJ;
    int b   = rem % dl;
    int a   = rem / dl;

    float accR = 0.0f;
    for (int i = 0; i < dj; i++) {
        float q1r, q1i; qmat_f(j, i, a, q1r, q1i);
        if (q1r == 0.0f && q1i == 0.0f) continue;
        int m1 = i - j;
        for (int k = 0; k < dl; k++) {
            int m2 = k - l, m3 = m1 + m2;
            if (m3 < -J || m3 > J) continue;
            float q2r, q2i; qmat_f(l, k, b, q2r, q2i);
            if (q2r == 0.0f && q2i == 0.0f) continue;
            float s = su2_cg_f(j, m1, l, m2, J, m3);
            if (s == 0.0f) continue;
            float q3r, q3i; qmat_f(J, J + m3, pp, q3r, q3i);
            q3i = -q3i;   // conj
            float tr = q1r*q2r - q1i*q2i, ti = q1r*q2i + q1i*q2r;
            accR += (tr*q3r - ti*q3i) * s;
        }
    }
    d_cg[gid] = accR;
}

// ---------------------------------------------------------------------------
// Init 2: build the 333-group sparse program (nnz padded to even)
// ---------------------------------------------------------------------------
struct Seg { signed char type, j, l; short cstart; };  // 0=D0(l=0),1=D1(j=0),2=CG,-1=end

__global__ void init_prog_kernel() {
    int g = blockIdx.x * blockDim.x + threadIdx.x;
    if (g >= NGROUPS) return;

    const int gcum[5]    = {0, 10, 73, 193, 333};
    const int gperrow[4] = {10, 21, 24, 20};
    const int chJ[4]     = {160, 336, 384, 320};
    const int yoff[4]    = {0, 4, 13, 23};
    const int coff[4]    = {0, 16, 64, 144};

    const Seg segJ0[] = {{0,0,0,0},{2,1,1,64},{2,2,2,112},{2,3,3,144},{-1,0,0,160}};
    const Seg segJ1[] = {{0,1,0,0},{1,0,1,48},{2,1,1,112},{2,2,1,160},{2,1,2,192},
                         {2,2,2,240},{2,3,2,272},{2,2,3,288},{2,3,3,320},{-1,0,0,336}};
    const Seg segJ2[] = {{0,2,0,0},{1,0,2,32},{2,1,1,96},{2,2,1,144},{2,3,1,176},
                         {2,1,2,192},{2,2,2,240},{2,3,2,272},{2,1,3,288},{2,2,3,336},
                         {2,3,3,368},{-1,0,0,384}};
    const Seg segJ3[] = {{0,3,0,0},{1,0,3,16},{2,2,1,80},{2,3,1,112},{2,1,2,128},
                         {2,2,2,176},{2,3,2,208},{2,1,3,224},{2,2,3,272},{2,3,3,304},
                         {-1,0,0,320}};
    const Seg* segs[4] = {segJ0, segJ1, segJ2, segJ3};

    int J  = (g < 10) ? 0 : (g < 73) ? 1 : (g < 193) ? 2 : 3;
    int rl = g - gcum[J];
    int p  = rl / gperrow[J];
    int c  = (rl % gperrow[J]) * 16;

    const Seg* st = segs[J];
    int si = 0;
    while (st[si + 1].type != -1 && st[si + 1].cstart <= c) si++;
    Seg sg = st[si];
    int cl = c - sg.cstart;
    int i  = cl >> 4;

    float2* out = &g_pairs[g * MAXNNZ];
    int n = 0;
    if (sg.type == 0) {              // l=0 direct, j=J
        out[n].x = 1.0f;
        out[n].y = __int_as_float((yoff[J] + p * (4 - J) + i) * 256);
        n++;
    } else if (sg.type == 1) {       // j=0 direct, l=J
        out[n].x = 1.0f;
        out[n].y = __int_as_float(i * 256 + coff[J] + p * 16);
        n++;
    } else {                         // CG contraction
        int j = sg.j, l = sg.l;
        int cb = combo_index(j, l, J) * 343;
        int dl = 2*l + 1, dJ = 2*J + 1;
        for (int nn = 0; nn < 2*j + 1; nn++)
            for (int m = 0; m < dl; m++) {
                float coef = d_cg[cb + (nn * dl + m) * dJ + p];
                if (fabsf(coef) > 1e-6f) {
                    out[n].x = coef;
                    out[n].y = __int_as_float((yoff[j] + nn * (4 - j) + i) * 256
                                              + coff[l] + m * 16);
                    n++;
                }
            }
    }
    if (n & 1) {                     // pad to even for float4 streaming
        out[n].x = 0.0f;
        out[n].y = __int_as_float(0);
        n++;
    }
    g_meta[g] = make_int2((J << 16) | (p * chJ[J] + c), n);
}

// ---------------------------------------------------------------------------
// Main kernel: one CTA (256 threads) per (b,v) — R1-proven structure
// ---------------------------------------------------------------------------
__global__ __launch_bounds__(256)
void conv_kernel(const float* __restrict__ x0, const float* __restrict__ x1,
                 const float* __restrict__ x2, const float* __restrict__ x3,
                 const int*   __restrict__ patches,
                 const float* __restrict__ kernels,
                 float* __restrict__ out)
{
    __shared__ float Ksm[32][32];            // K[p][y], padded to 32
    __shared__ int   rowIdx[32];
    __shared__ __align__(16) float ysm[30 * 256];

    const int bv  = blockIdx.x;
    const int tid = threadIdx.x;

    // stage K (32x30) and patch row indices
    const float* kp = kernels + (size_t)bv * (P_ * 30);
    for (int t = tid; t < P_ * 30; t += 256) {
        int pr = t / 30;
        Ksm[pr][t - pr * 30] = kp[t];
    }
    if (tid < P_) {
        int2 pi = ((const int2*)patches)[(size_t)bv * P_ + tid];
        rowIdx[tid] = pi.x * N_ + pi.y;
    }

    // column -> source decode (thread owns channel column tid)
    const float* xb; int rowlen, cloc;
    if (tid < 16)       { xb = x0; rowlen = 16;  cloc = tid;       }
    else if (tid < 64)  { xb = x1; rowlen = 48;  cloc = tid - 16;  }
    else if (tid < 144) { xb = x2; rowlen = 80;  cloc = tid - 64;  }
    else                { xb = x3; rowlen = 112; cloc = tid - 144; }

    __syncthreads();

    // y[yrow, c=tid] = sum_p K[p,yrow] * g[p,c]
    float acc[30];
    #pragma unroll
    for (int y = 0; y < 30; y++) acc[y] = 0.0f;

    #pragma unroll 4
    for (int p = 0; p < P_; p++) {
        float gv = __ldg(xb + (long)rowIdx[p] * rowlen + cloc);
        #pragma unroll
        for (int y = 0; y < 30; y++)
            acc[y] = fmaf(Ksm[p][y], gv, acc[y]);
    }

    #pragma unroll
    for (int y = 0; y < 30; y++) ysm[y * 256 + tid] = acc[y];
    __syncthreads();

    // epilogue: 333 groups x 4 quarters; 2 coefficient pairs per 16B load
    const size_t outBase[4] = {0, 1310720, 9568256, 25296896};
    const int    slab[4]    = {160, 1008, 1920, 2240};

    for (int item = tid; item < NGROUPS * 4; item += 256) {
        int g = item >> 2, q = item & 3;
        int2 gm = g_meta[g];
        int nnz = gm.y;                            // even
        const float4* pr4 = (const float4*)&g_pairs[g * MAXNNZ];
        const float* ybase = ysm + q * 4;
        float4 a = make_float4(0.f, 0.f, 0.f, 0.f);
        for (int k = 0; k < nnz; k += 2) {
            float4 rec = pr4[k >> 1];              // {c0, yb0, c1, yb1}
            const float4 v0 = *(const float4*)&ybase[__float_as_int(rec.y)];
            const float4 v1 = *(const float4*)&ybase[__float_as_int(rec.w)];
            a.x = fmaf(rec.x, v0.x, a.x);
            a.y = fmaf(rec.x, v0.y, a.y);
            a.z = fmaf(rec.x, v0.z, a.z);
            a.w = fmaf(rec.x, v0.w, a.w);
            a.x = fmaf(rec.z, v1.x, a.x);
            a.y = fmaf(rec.z, v1.y, a.y);
            a.z = fmaf(rec.z, v1.z, a.z);
            a.w = fmaf(rec.z, v1.w, a.w);
        }
        int J = gm.x >> 16;
        int local = gm.x & 0xffff;
        size_t off = outBase[J] + (size_t)bv * slab[J] + local + q * 4;
        *(float4*)&out[off] = a;
    }
}

// ---------------------------------------------------------------------------
extern "C" void kernel_launch(void* const* d_in, const int* in_sizes, int n_in,
                              void* d_out, int out_size) {
    const float* x0      = (const float*)d_in[0];
    const float* x1      = (const float*)d_in[1];
    const float* x2      = (const float*)d_in[2];
    const float* x3      = (const float*)d_in[3];
    const int*   patches = (const int*)d_in[4];
    const float* kernels = (const float*)d_in[5];
    float*       out     = (float*)d_out;

    init_cg_kernel<<<(27 * 343 + 127) / 128, 128>>>();
    init_prog_kernel<<<3, 128>>>();
    conv_kernel<<<BV_, 256>>>(x0, x1, x2, x3, patches, kernels, out);
}